// round 11
// baseline (speedup 1.0000x reference)
#include <cuda_runtime.h>
#include <math.h>

#define TT 512
#define BB 256
#define DD 256
#define HH 256
#define KK 256
#define GG 1024  // 4*H

#define NBLK 256     // persistent grid for recurrence
#define NTHR 128

// Scratch state (static device globals: allocation-free per harness rules)
__device__ float g_gx[(size_t)TT * BB * GG];   // precomputed x-path gates + biases
__device__ float2 g_asp[(size_t)TT * BB * DD]; // (hi,lo) tf32 split of X.*mask_x
__device__ float2 g_wsp[(size_t)GG * DD];      // (hi,lo) tf32 split of W_ih
__device__ float g_hm[2][BB * HH];             // double-buffered (h .* mask_h)
__device__ unsigned g_bar = 0;                 // grid barrier counter
__device__ unsigned g_gen = 0;                 // grid barrier generation

// ===========================================================================
// Split-tf32 helpers (sm_80+ mma.sync — valid on sm_100a)
// ===========================================================================
__device__ __forceinline__ unsigned f2tf(float a) {
    unsigned r;
    asm("cvt.rna.tf32.f32 %0, %1;" : "=r"(r) : "f"(a));
    return r;
}
__device__ __forceinline__ float2 split2(float a) {
    unsigned h = f2tf(a);
    unsigned l = f2tf(a - __uint_as_float(h));
    return make_float2(__uint_as_float(h), __uint_as_float(l));
}
__device__ __forceinline__ void mma_tf32(float* c, const unsigned* a,
                                         unsigned b0, unsigned b1) {
    asm("mma.sync.aligned.m16n8k8.row.col.f32.tf32.tf32.f32 "
        "{%0,%1,%2,%3}, {%4,%5,%6,%7}, {%8,%9}, {%0,%1,%2,%3};"
        : "+f"(c[0]), "+f"(c[1]), "+f"(c[2]), "+f"(c[3])
        : "r"(a[0]), "r"(a[1]), "r"(a[2]), "r"(a[3]), "r"(b0), "r"(b1));
}

// ---------------------------------------------------------------------------
// prep_a: g_asp[e] = tf32_split(X[e] * MX[(row%B), d]). One split per element.
//   Grid covers T*B*D/4 float4s exactly (32768 blocks x 256 thr).
// ---------------------------------------------------------------------------
__global__ __launch_bounds__(256) void prep_a(
    const float* __restrict__ X, const float* __restrict__ MX)
{
    const size_t i4 = (size_t)blockIdx.x * 256 + threadIdx.x;
    const size_t e = i4 * 4;
    const int b = (int)((e / DD) & (BB - 1));
    const int d = (int)(e % DD);
    float4 xv = *(const float4*)(X + e);
    float4 mv = *(const float4*)(MX + (size_t)b * DD + d);
    float2 s0 = split2(xv.x * mv.x);
    float2 s1 = split2(xv.y * mv.y);
    float2 s2 = split2(xv.z * mv.z);
    float2 s3 = split2(xv.w * mv.w);
    *(float4*)&g_asp[e]     = make_float4(s0.x, s0.y, s1.x, s1.y);
    *(float4*)&g_asp[e + 2] = make_float4(s2.x, s2.y, s3.x, s3.y);
}

// prep_w: same for W_ih (4H x D). 256 blocks x 256 thr covers GG*DD/4.
__global__ __launch_bounds__(256) void prep_w(const float* __restrict__ W)
{
    const size_t e = ((size_t)blockIdx.x * 256 + threadIdx.x) * 4;
    float4 wv = *(const float4*)(W + e);
    float2 s0 = split2(wv.x);
    float2 s1 = split2(wv.y);
    float2 s2 = split2(wv.z);
    float2 s3 = split2(wv.w);
    *(float4*)&g_wsp[e]     = make_float4(s0.x, s0.y, s1.x, s1.y);
    *(float4*)&g_wsp[e + 2] = make_float4(s2.x, s2.y, s3.x, s3.y);
}

// ---------------------------------------------------------------------------
// gemm_x_tc2: pure-MMA split-tf32 GEMM (no cvt in the loop).
//   g_gx[m,n] = sum_k A[m,k]*W[n,k] + bih[n] + bhh[n], 3-term split product.
//   CTA tile 128x64, 8 warps of 16x64, K-chunk 16 (16 iterations).
//   smem stride 20: fragment banks g*20+tg mod 32 cover 0..31 exactly.
// ---------------------------------------------------------------------------
__global__ __launch_bounds__(256) void gemm_x_tc2(
    const float* __restrict__ bih, const float* __restrict__ bhh)
{
    __shared__ float Ah[128][20], Al[128][20];   // 20.5 KB
    __shared__ float Bh[64][20],  Bl[64][20];    // 10.2 KB

    const int m0 = blockIdx.x * 128;
    const int n0 = blockIdx.y * 64;
    const int tid = threadIdx.x;
    const int warp = tid >> 5;
    const int lane = tid & 31;
    const int g = lane >> 2;        // 0..7
    const int tg = lane & 3;        // 0..3
    const int wm = warp * 16;

    float acc[8][4];
#pragma unroll
    for (int nt = 0; nt < 8; nt++)
#pragma unroll
        for (int i = 0; i < 4; i++) acc[nt][i] = 0.0f;

    for (int kc = 0; kc < 16; kc++) {
        const int k0 = kc * 16;
        __syncthreads();
        // A chunk: 128 rows x 16 k = 2048 (hi,lo) pairs = 1024 float4
#pragma unroll
        for (int q = 0; q < 4; q++) {
            int i = tid + 256 * q;          // 0..1023
            int row = i >> 3;               // 8 float4 per row (16 elems)
            int kp = (i & 7) * 2;
            float4 v = *(const float4*)&g_asp[(size_t)(m0 + row) * KK + k0 + kp];
            Ah[row][kp] = v.x;  Al[row][kp] = v.y;
            Ah[row][kp + 1] = v.z;  Al[row][kp + 1] = v.w;
        }
        // B chunk: 64 rows x 16 k = 1024 pairs = 512 float4
#pragma unroll
        for (int q = 0; q < 2; q++) {
            int i = tid + 256 * q;          // 0..511
            int row = i >> 3;
            int kp = (i & 7) * 2;
            float4 v = *(const float4*)&g_wsp[(size_t)(n0 + row) * KK + k0 + kp];
            Bh[row][kp] = v.x;  Bl[row][kp] = v.y;
            Bh[row][kp + 1] = v.z;  Bl[row][kp + 1] = v.w;
        }
        __syncthreads();

#pragma unroll
        for (int ks = 0; ks < 2; ks++) {
            const int kk = ks * 8;
            unsigned ah[4], al[4];
            ah[0] = __float_as_uint(Ah[wm + g][kk + tg]);
            ah[1] = __float_as_uint(Ah[wm + g + 8][kk + tg]);
            ah[2] = __float_as_uint(Ah[wm + g][kk + tg + 4]);
            ah[3] = __float_as_uint(Ah[wm + g + 8][kk + tg + 4]);
            al[0] = __float_as_uint(Al[wm + g][kk + tg]);
            al[1] = __float_as_uint(Al[wm + g + 8][kk + tg]);
            al[2] = __float_as_uint(Al[wm + g][kk + tg + 4]);
            al[3] = __float_as_uint(Al[wm + g + 8][kk + tg + 4]);
#pragma unroll
            for (int nt = 0; nt < 8; nt++) {
                unsigned bh0 = __float_as_uint(Bh[nt * 8 + g][kk + tg]);
                unsigned bh1 = __float_as_uint(Bh[nt * 8 + g][kk + tg + 4]);
                unsigned bl0 = __float_as_uint(Bl[nt * 8 + g][kk + tg]);
                unsigned bl1 = __float_as_uint(Bl[nt * 8 + g][kk + tg + 4]);
                mma_tf32(acc[nt], ah, bh0, bh1);   // hi*hi
                mma_tf32(acc[nt], ah, bl0, bl1);   // hi*lo
                mma_tf32(acc[nt], al, bh0, bh1);   // lo*hi
            }
        }
    }

    // epilogue: add biases, store float2 pairs
#pragma unroll
    for (int nt = 0; nt < 8; nt++) {
        const int n = n0 + nt * 8 + tg * 2;
        const float bs0 = bih[n] + bhh[n];
        const float bs1 = bih[n + 1] + bhh[n + 1];
        const int m = m0 + wm + g;
        float2 r0 = make_float2(acc[nt][0] + bs0, acc[nt][1] + bs1);
        float2 r1 = make_float2(acc[nt][2] + bs0, acc[nt][3] + bs1);
        *(float2*)&g_gx[(size_t)m * GG + n] = r0;
        *(float2*)&g_gx[(size_t)(m + 8) * GG + n] = r1;
    }
}

// ---------------------------------------------------------------------------
// Grid-wide barrier (R5/R10-proven form). Co-residency: __launch_bounds__(NTHR,2).
// ---------------------------------------------------------------------------
__device__ __forceinline__ void grid_barrier()
{
    __threadfence();
    __syncthreads();
    if (threadIdx.x == 0) {
        unsigned gen = *(volatile unsigned*)&g_gen;
        if (atomicAdd(&g_bar, 1u) == (unsigned)(NBLK - 1)) {
            g_bar = 0;
            __threadfence();
            *(volatile unsigned*)&g_gen = gen + 1;
        } else {
            while (*(volatile unsigned*)&g_gen == gen) { }
        }
    }
    __syncthreads();
}

__device__ __forceinline__ float fsig(float x) {
    return __fdividef(1.0f, 1.0f + __expf(-x));
}
__device__ __forceinline__ float ftanh(float x) {
    return __fdividef(2.0f, 1.0f + __expf(-2.0f * x)) - 1.0f;
}

// ---------------------------------------------------------------------------
// Persistent recurrent kernel — byte-identical to R10's passing version.
// ---------------------------------------------------------------------------
__global__ __launch_bounds__(NTHR, 2) void recurrent_kernel(
    const float* __restrict__ mh, const float* __restrict__ Whh,
    const int* __restrict__ bsz, const float* __restrict__ h0,
    const float* __restrict__ c0, float* __restrict__ out)
{
    __shared__ __align__(16) float Ws[KK][8][4];  // [k][jl][gate] 32 KB
    __shared__ float As[2][32][34];               // hm chunk [k][row], padded
    __shared__ int   Sbsz[TT];                    // 2 KB (total ~43 KB)

    const int bb = blockIdx.x >> 5;
    const int cb = blockIdx.x & 31;
    const int b0 = bb * 32;
    const int j0 = cb * 8;
    const int tid = threadIdx.x;
    const int tx = tid & 7;
    const int ty = tid >> 3;
    const int r0 = b0 + ty * 2;
    const int j = j0 + tx;

    for (int rr = tid >> 5; rr < 32; rr += 4) {
        int g = rr >> 3, jl = rr & 7;
        const float* src = Whh + (size_t)(g * 256 + j0 + jl) * KK;
        for (int k = (tid & 31); k < KK; k += 32)
            Ws[k][jl][g] = src[k];
    }
    for (int i = tid; i < TT; i += NTHR) Sbsz[i] = bsz[i];

    float mhv[2], cc[2], hh[2];
#pragma unroll
    for (int r = 0; r < 2; r++) {
        int b = r0 + r;
        mhv[r] = mh[b * HH + j];
        cc[r] = c0[b * HH + j];
        hh[r] = h0[b * HH + j];
        g_hm[0][b * HH + j] = hh[r] * mhv[r];
    }
    __syncthreads();
    grid_barrier();

    const int lr = tid >> 2;
    const int lk = (tid & 3) * 8;
    const size_t hoff = (size_t)(b0 + lr) * HH + lk;

    float gx0[4], gx1[4];
    {
        const float* gp = g_gx + (size_t)r0 * GG + j;
#pragma unroll
        for (int g = 0; g < 4; g++) {
            gx0[g] = __ldcg(gp + g * 256);
            gx1[g] = __ldcg(gp + GG + g * 256);
        }
    }

    for (int t = 0; t < TT; t++) {
        const float* __restrict__ hmp = g_hm[t & 1];
        float* __restrict__ hmn = g_hm[(t & 1) ^ 1];
        const float* hrow = hmp + hoff;

        float a00 = gx0[0], a01 = gx0[1], a02 = gx0[2], a03 = gx0[3];
        float a10 = gx1[0], a11 = gx1[1], a12 = gx1[2], a13 = gx1[3];

        float4 p0 = __ldcg((const float4*)(hrow + 0));
        float4 p1 = __ldcg((const float4*)(hrow + 4));
#pragma unroll
        for (int i = 0; i < 4; i++) {
            As[0][lk + i][lr] = ((const float*)&p0)[i];
            As[0][lk + 4 + i][lr] = ((const float*)&p1)[i];
        }
        __syncthreads();

#pragma unroll
        for (int c = 0; c < 8; c++) {
            const int buf = c & 1;
            if (c < 7) {
                p0 = __ldcg((const float4*)(hrow + (c + 1) * 32));
                p1 = __ldcg((const float4*)(hrow + (c + 1) * 32 + 4));
            }
            const int kb = c * 32;
#pragma unroll
            for (int k = 0; k < 32; k++) {
                float2 a = *(const float2*)&As[buf][k][ty * 2];
                const float4 w = *(const float4*)&Ws[kb + k][tx][0];
                a00 = fmaf(a.x, w.x, a00); a01 = fmaf(a.x, w.y, a01);
                a02 = fmaf(a.x, w.z, a02); a03 = fmaf(a.x, w.w, a03);
                a10 = fmaf(a.y, w.x, a10); a11 = fmaf(a.y, w.y, a11);
                a12 = fmaf(a.y, w.z, a12); a13 = fmaf(a.y, w.w, a13);
            }
            if (c < 7) {
#pragma unroll
                for (int i = 0; i < 4; i++) {
                    As[buf ^ 1][lk + i][lr] = ((const float*)&p0)[i];
                    As[buf ^ 1][lk + 4 + i][lr] = ((const float*)&p1)[i];
                }
                __syncthreads();
            }
        }

        const int size = Sbsz[t];
        float o0, o1;
        {
            float iv = fsig(a00), fv = fsig(a01), gv = ftanh(a02), ov = fsig(a03);
            float cn = fv * cc[0] + iv * gv;
            float hn = ov * ftanh(cn);
            bool act = r0 < size;
            if (act) { cc[0] = cn; hh[0] = hn; }
            o0 = act ? hn : 0.0f;
            hmn[r0 * HH + j] = hh[0] * mhv[0];
        }
        {
            float iv = fsig(a10), fv = fsig(a11), gv = ftanh(a12), ov = fsig(a13);
            float cn = fv * cc[1] + iv * gv;
            float hn = ov * ftanh(cn);
            bool act = (r0 + 1) < size;
            if (act) { cc[1] = cn; hh[1] = hn; }
            o1 = act ? hn : 0.0f;
            hmn[(r0 + 1) * HH + j] = hh[1] * mhv[1];
        }

        if (t + 1 < TT) {
            const float* gp = g_gx + ((size_t)(t + 1) * BB + r0) * GG + j;
#pragma unroll
            for (int g = 0; g < 4; g++) {
                gx0[g] = __ldcg(gp + g * 256);
                gx1[g] = __ldcg(gp + GG + g * 256);
            }
        }

        grid_barrier();

        out[((size_t)t * BB + r0) * HH + j] = o0;
        out[((size_t)t * BB + r0 + 1) * HH + j] = o1;
    }

    const size_t TBH = (size_t)TT * BB * HH;
#pragma unroll
    for (int r = 0; r < 2; r++) {
        int b = r0 + r;
        out[TBH + b * HH + j] = hh[r];
        out[TBH + BB * HH + b * HH + j] = cc[r];
    }
}

// ---------------------------------------------------------------------------
extern "C" void kernel_launch(void* const* d_in, const int* in_sizes, int n_in,
                              void* d_out, int out_size)
{
    const float* X   = (const float*)d_in[0];   // [T,B,D]
    const float* h0  = (const float*)d_in[1];   // [B,H]
    const float* c0  = (const float*)d_in[2];   // [B,H]
    const float* mx  = (const float*)d_in[3];   // [B,D]
    const float* mh  = (const float*)d_in[4];   // [B,H]
    const float* Wih = (const float*)d_in[5];   // [4H,D]
    const float* Whh = (const float*)d_in[6];   // [4H,H]
    const float* bih = (const float*)d_in[7];   // [4H]
    const float* bhh = (const float*)d_in[8];   // [4H]
    const int*   bsz = (const int*)d_in[9];     // [T]
    float* out = (float*)d_out;                 // [T*B*H] ++ [B*H] ++ [B*H]

    prep_a<<<(TT * BB * DD / 4) / 256, 256>>>(X, mx);
    prep_w<<<(GG * DD / 4) / 256, 256>>>(Wih);
    gemm_x_tc2<<<dim3((TT * BB) / 128, GG / 64), 256>>>(bih, bhh);
    recurrent_kernel<<<NBLK, NTHR>>>(mh, Whh, bsz, h0, c0, out);
}

// round 12
// speedup vs baseline: 1.1393x; 1.1393x over previous
#include <cuda_runtime.h>
#include <math.h>

#define TT 512
#define BB 256
#define DD 256
#define HH 256
#define KK 256
#define GG 1024  // 4*H

#define NBLK 256     // persistent grid for recurrence
#define NTHR 128

// Scratch state (static device globals: allocation-free per harness rules)
__device__ float g_gx[(size_t)TT * BB * GG];   // precomputed x-path gates + biases
__device__ float g_hm[2][BB * HH];             // double-buffered (h .* mask_h)
__device__ unsigned g_bar = 0;                 // grid barrier counter
__device__ unsigned g_gen = 0;                 // grid barrier generation

// ===========================================================================
// Split-tf32 helpers (sm_80+ mma.sync — valid on sm_100a)
// ===========================================================================
__device__ __forceinline__ unsigned f2tf(float a) {
    unsigned r;
    asm("cvt.rna.tf32.f32 %0, %1;" : "=r"(r) : "f"(a));
    return r;
}
__device__ __forceinline__ void split_tf32(float a, unsigned& h, unsigned& l) {
    h = f2tf(a);
    l = f2tf(a - __uint_as_float(h));
}
__device__ __forceinline__ void mma_tf32(float* c, const unsigned* a,
                                         unsigned b0, unsigned b1) {
    asm("mma.sync.aligned.m16n8k8.row.col.f32.tf32.tf32.f32 "
        "{%0,%1,%2,%3}, {%4,%5,%6,%7}, {%8,%9}, {%0,%1,%2,%3};"
        : "+f"(c[0]), "+f"(c[1]), "+f"(c[2]), "+f"(c[3])
        : "r"(a[0]), "r"(a[1]), "r"(a[2]), "r"(a[3]), "r"(b0), "r"(b1));
}

// ---------------------------------------------------------------------------
// gemm_x (split-tf32 3-term, R10 structure + B pre-split at load):
//   g_gx[m,n] = sum_k X[m,k]*MX[m&255,k] * W[n,k] + bih[n] + bhh[n]
//   CTA tile 128x64, 8 warps of 16x64, K-chunk 32.
//   B is split hi/lo ONCE by the loader (was: re-split by all 8 warps in-loop).
//   A stays raw in smem (float4 STS), split in-loop (non-redundant).
//   Fragment reads conflict-free via stride-36 (bank = 4g+tg+c, a permutation).
// ---------------------------------------------------------------------------
__global__ __launch_bounds__(256) void gemm_x_tc(
    const float* __restrict__ X, const float* __restrict__ MX,
    const float* __restrict__ W, const float* __restrict__ bih,
    const float* __restrict__ bhh)
{
    __shared__ float As[128][36];                // raw A chunk, 18 KB
    __shared__ float Bh[64][36], Bl[64][36];     // pre-split B chunk, 18 KB

    const int m0 = blockIdx.x * 128;
    const int n0 = blockIdx.y * 64;
    const int tid = threadIdx.x;
    const int warp = tid >> 5;
    const int lane = tid & 31;
    const int g = lane >> 2;        // 0..7
    const int tg = lane & 3;        // 0..3
    const int wm = warp * 16;       // warp's M offset within CTA tile

    float acc[8][4];
#pragma unroll
    for (int nt = 0; nt < 8; nt++)
#pragma unroll
        for (int i = 0; i < 4; i++) acc[nt][i] = 0.0f;

    for (int kc = 0; kc < 8; kc++) {
        const int k0 = kc * 32;
        __syncthreads();
        // A chunk: 128 rows x 32 k, float4 STS, masked by MX (unchanged from R10)
#pragma unroll
        for (int q = 0; q < 4; q++) {
            int i = tid + 256 * q;          // 0..1023 float4 slots
            int row = i >> 3;               // 8 float4 per row
            int kq = (i & 7) * 4;
            float4 xv = *(const float4*)(X + (size_t)(m0 + row) * KK + k0 + kq);
            float4 mv = *(const float4*)(MX + (size_t)((m0 + row) & (BB - 1)) * KK + k0 + kq);
            xv.x *= mv.x; xv.y *= mv.y; xv.z *= mv.z; xv.w *= mv.w;
            *(float4*)&As[row][kq] = xv;
        }
        // B chunk: 64 rows x 32 k — split hi/lo ONCE here
#pragma unroll
        for (int q = 0; q < 2; q++) {
            int i = tid + 256 * q;          // 0..511
            int row = i >> 3;
            int kq = (i & 7) * 4;
            float4 wv = *(const float4*)(W + (size_t)(n0 + row) * KK + k0 + kq);
            unsigned h, l;
            split_tf32(wv.x, h, l);
            Bh[row][kq]     = __uint_as_float(h); Bl[row][kq]     = __uint_as_float(l);
            split_tf32(wv.y, h, l);
            Bh[row][kq + 1] = __uint_as_float(h); Bl[row][kq + 1] = __uint_as_float(l);
            split_tf32(wv.z, h, l);
            Bh[row][kq + 2] = __uint_as_float(h); Bl[row][kq + 2] = __uint_as_float(l);
            split_tf32(wv.w, h, l);
            Bh[row][kq + 3] = __uint_as_float(h); Bl[row][kq + 3] = __uint_as_float(l);
        }
        __syncthreads();

#pragma unroll
        for (int ks = 0; ks < 4; ks++) {
            const int kk = ks * 8;
            // A fragment (m16 x k8), split hi/lo in-loop (one split per use)
            unsigned ah[4], al[4];
            split_tf32(As[wm + g][kk + tg],         ah[0], al[0]);
            split_tf32(As[wm + g + 8][kk + tg],     ah[1], al[1]);
            split_tf32(As[wm + g][kk + tg + 4],     ah[2], al[2]);
            split_tf32(As[wm + g + 8][kk + tg + 4], ah[3], al[3]);
#pragma unroll
            for (int nt = 0; nt < 8; nt++) {
                unsigned bh0 = __float_as_uint(Bh[nt * 8 + g][kk + tg]);
                unsigned bh1 = __float_as_uint(Bh[nt * 8 + g][kk + tg + 4]);
                unsigned bl0 = __float_as_uint(Bl[nt * 8 + g][kk + tg]);
                unsigned bl1 = __float_as_uint(Bl[nt * 8 + g][kk + tg + 4]);
                mma_tf32(acc[nt], ah, bh0, bh1);   // hi*hi
                mma_tf32(acc[nt], ah, bl0, bl1);   // hi*lo
                mma_tf32(acc[nt], al, bh0, bh1);   // lo*hi
            }
        }
    }

    // epilogue: add biases, store float2 pairs
#pragma unroll
    for (int nt = 0; nt < 8; nt++) {
        const int n = n0 + nt * 8 + tg * 2;
        const float bs0 = bih[n] + bhh[n];
        const float bs1 = bih[n + 1] + bhh[n + 1];
        const int m = m0 + wm + g;
        float2 r0 = make_float2(acc[nt][0] + bs0, acc[nt][1] + bs1);
        float2 r1 = make_float2(acc[nt][2] + bs0, acc[nt][3] + bs1);
        *(float2*)&g_gx[(size_t)m * GG + n] = r0;
        *(float2*)&g_gx[(size_t)(m + 8) * GG + n] = r1;
    }
}

// ---------------------------------------------------------------------------
// Grid-wide barrier (R5/R10-proven form). Co-residency: __launch_bounds__(NTHR,2).
// ---------------------------------------------------------------------------
__device__ __forceinline__ void grid_barrier()
{
    __threadfence();
    __syncthreads();
    if (threadIdx.x == 0) {
        unsigned gen = *(volatile unsigned*)&g_gen;
        if (atomicAdd(&g_bar, 1u) == (unsigned)(NBLK - 1)) {
            g_bar = 0;
            __threadfence();
            *(volatile unsigned*)&g_gen = gen + 1;
        } else {
            while (*(volatile unsigned*)&g_gen == gen) { }
        }
    }
    __syncthreads();
}

__device__ __forceinline__ float fsig(float x) {
    return __fdividef(1.0f, 1.0f + __expf(-x));
}
__device__ __forceinline__ float ftanh(float x) {
    return __fdividef(2.0f, 1.0f + __expf(-2.0f * x)) - 1.0f;
}

// ---------------------------------------------------------------------------
// Persistent recurrent kernel — byte-identical to R10's passing version.
// ---------------------------------------------------------------------------
__global__ __launch_bounds__(NTHR, 2) void recurrent_kernel(
    const float* __restrict__ mh, const float* __restrict__ Whh,
    const int* __restrict__ bsz, const float* __restrict__ h0,
    const float* __restrict__ c0, float* __restrict__ out)
{
    __shared__ __align__(16) float Ws[KK][8][4];  // [k][jl][gate] 32 KB
    __shared__ float As[2][32][34];               // hm chunk [k][row], padded
    __shared__ int   Sbsz[TT];                    // 2 KB (total ~43 KB)

    const int bb = blockIdx.x >> 5;
    const int cb = blockIdx.x & 31;
    const int b0 = bb * 32;
    const int j0 = cb * 8;
    const int tid = threadIdx.x;
    const int tx = tid & 7;
    const int ty = tid >> 3;
    const int r0 = b0 + ty * 2;
    const int j = j0 + tx;

    for (int rr = tid >> 5; rr < 32; rr += 4) {
        int g = rr >> 3, jl = rr & 7;
        const float* src = Whh + (size_t)(g * 256 + j0 + jl) * KK;
        for (int k = (tid & 31); k < KK; k += 32)
            Ws[k][jl][g] = src[k];
    }
    for (int i = tid; i < TT; i += NTHR) Sbsz[i] = bsz[i];

    float mhv[2], cc[2], hh[2];
#pragma unroll
    for (int r = 0; r < 2; r++) {
        int b = r0 + r;
        mhv[r] = mh[b * HH + j];
        cc[r] = c0[b * HH + j];
        hh[r] = h0[b * HH + j];
        g_hm[0][b * HH + j] = hh[r] * mhv[r];
    }
    __syncthreads();
    grid_barrier();

    const int lr = tid >> 2;
    const int lk = (tid & 3) * 8;
    const size_t hoff = (size_t)(b0 + lr) * HH + lk;

    float gx0[4], gx1[4];
    {
        const float* gp = g_gx + (size_t)r0 * GG + j;
#pragma unroll
        for (int g = 0; g < 4; g++) {
            gx0[g] = __ldcg(gp + g * 256);
            gx1[g] = __ldcg(gp + GG + g * 256);
        }
    }

    for (int t = 0; t < TT; t++) {
        const float* __restrict__ hmp = g_hm[t & 1];
        float* __restrict__ hmn = g_hm[(t & 1) ^ 1];
        const float* hrow = hmp + hoff;

        float a00 = gx0[0], a01 = gx0[1], a02 = gx0[2], a03 = gx0[3];
        float a10 = gx1[0], a11 = gx1[1], a12 = gx1[2], a13 = gx1[3];

        float4 p0 = __ldcg((const float4*)(hrow + 0));
        float4 p1 = __ldcg((const float4*)(hrow + 4));
#pragma unroll
        for (int i = 0; i < 4; i++) {
            As[0][lk + i][lr] = ((const float*)&p0)[i];
            As[0][lk + 4 + i][lr] = ((const float*)&p1)[i];
        }
        __syncthreads();

#pragma unroll
        for (int c = 0; c < 8; c++) {
            const int buf = c & 1;
            if (c < 7) {
                p0 = __ldcg((const float4*)(hrow + (c + 1) * 32));
                p1 = __ldcg((const float4*)(hrow + (c + 1) * 32 + 4));
            }
            const int kb = c * 32;
#pragma unroll
            for (int k = 0; k < 32; k++) {
                float2 a = *(const float2*)&As[buf][k][ty * 2];
                const float4 w = *(const float4*)&Ws[kb + k][tx][0];
                a00 = fmaf(a.x, w.x, a00); a01 = fmaf(a.x, w.y, a01);
                a02 = fmaf(a.x, w.z, a02); a03 = fmaf(a.x, w.w, a03);
                a10 = fmaf(a.y, w.x, a10); a11 = fmaf(a.y, w.y, a11);
                a12 = fmaf(a.y, w.z, a12); a13 = fmaf(a.y, w.w, a13);
            }
            if (c < 7) {
#pragma unroll
                for (int i = 0; i < 4; i++) {
                    As[buf ^ 1][lk + i][lr] = ((const float*)&p0)[i];
                    As[buf ^ 1][lk + 4 + i][lr] = ((const float*)&p1)[i];
                }
                __syncthreads();
            }
        }

        const int size = Sbsz[t];
        float o0, o1;
        {
            float iv = fsig(a00), fv = fsig(a01), gv = ftanh(a02), ov = fsig(a03);
            float cn = fv * cc[0] + iv * gv;
            float hn = ov * ftanh(cn);
            bool act = r0 < size;
            if (act) { cc[0] = cn; hh[0] = hn; }
            o0 = act ? hn : 0.0f;
            hmn[r0 * HH + j] = hh[0] * mhv[0];
        }
        {
            float iv = fsig(a10), fv = fsig(a11), gv = ftanh(a12), ov = fsig(a13);
            float cn = fv * cc[1] + iv * gv;
            float hn = ov * ftanh(cn);
            bool act = (r0 + 1) < size;
            if (act) { cc[1] = cn; hh[1] = hn; }
            o1 = act ? hn : 0.0f;
            hmn[(r0 + 1) * HH + j] = hh[1] * mhv[1];
        }

        if (t + 1 < TT) {
            const float* gp = g_gx + ((size_t)(t + 1) * BB + r0) * GG + j;
#pragma unroll
            for (int g = 0; g < 4; g++) {
                gx0[g] = __ldcg(gp + g * 256);
                gx1[g] = __ldcg(gp + GG + g * 256);
            }
        }

        grid_barrier();

        out[((size_t)t * BB + r0) * HH + j] = o0;
        out[((size_t)t * BB + r0 + 1) * HH + j] = o1;
    }

    const size_t TBH = (size_t)TT * BB * HH;
#pragma unroll
    for (int r = 0; r < 2; r++) {
        int b = r0 + r;
        out[TBH + b * HH + j] = hh[r];
        out[TBH + BB * HH + b * HH + j] = cc[r];
    }
}

// ---------------------------------------------------------------------------
extern "C" void kernel_launch(void* const* d_in, const int* in_sizes, int n_in,
                              void* d_out, int out_size)
{
    const float* X   = (const float*)d_in[0];   // [T,B,D]
    const float* h0  = (const float*)d_in[1];   // [B,H]
    const float* c0  = (const float*)d_in[2];   // [B,H]
    const float* mx  = (const float*)d_in[3];   // [B,D]
    const float* mh  = (const float*)d_in[4];   // [B,H]
    const float* Wih = (const float*)d_in[5];   // [4H,D]
    const float* Whh = (const float*)d_in[6];   // [4H,H]
    const float* bih = (const float*)d_in[7];   // [4H]
    const float* bhh = (const float*)d_in[8];   // [4H]
    const int*   bsz = (const int*)d_in[9];     // [T]
    float* out = (float*)d_out;                 // [T*B*H] ++ [B*H] ++ [B*H]

    gemm_x_tc<<<dim3((TT * BB) / 128, GG / 64), 256>>>(X, mx, Wih, bih, bhh);
    recurrent_kernel<<<NBLK, NTHR>>>(mh, Whh, bsz, h0, c0, out);
}

// round 13
// speedup vs baseline: 1.3982x; 1.2273x over previous
#include <cuda_runtime.h>
#include <math.h>

#define TT 512
#define BB 256
#define DD 256
#define HH 256
#define KK 256
#define GG 1024  // 4*H

#define RBLK 128     // persistent recurrence grid: 8 batch-groups x 16 n-blocks
#define RTHR 256

// Scratch state (static device globals: allocation-free per harness rules)
__device__ float g_gx[(size_t)TT * BB * GG];   // precomputed x-path gates + biases
__device__ float g_hm[2][BB * HH];             // double-buffered (h .* mask_h)
__device__ unsigned g_bar = 0;                 // grid barrier counter
__device__ unsigned g_gen = 0;                 // grid barrier generation

// ===========================================================================
// Split-tf32 helpers (sm_80+ mma.sync — valid on sm_100a)
// ===========================================================================
__device__ __forceinline__ unsigned f2tf(float a) {
    unsigned r;
    asm("cvt.rna.tf32.f32 %0, %1;" : "=r"(r) : "f"(a));
    return r;
}
__device__ __forceinline__ void split_tf32(float a, unsigned& h, unsigned& l) {
    h = f2tf(a);
    l = f2tf(a - __uint_as_float(h));
}
__device__ __forceinline__ void mma_tf32(float* c, const unsigned* a,
                                         unsigned b0, unsigned b1) {
    asm("mma.sync.aligned.m16n8k8.row.col.f32.tf32.tf32.f32 "
        "{%0,%1,%2,%3}, {%4,%5,%6,%7}, {%8,%9}, {%0,%1,%2,%3};"
        : "+f"(c[0]), "+f"(c[1]), "+f"(c[2]), "+f"(c[3])
        : "r"(a[0]), "r"(a[1]), "r"(a[2]), "r"(a[3]), "r"(b0), "r"(b1));
}

// ---------------------------------------------------------------------------
// gemm_x — R12 verbatim (passed, rel_err 1.68e-6).
// ---------------------------------------------------------------------------
__global__ __launch_bounds__(256) void gemm_x_tc(
    const float* __restrict__ X, const float* __restrict__ MX,
    const float* __restrict__ W, const float* __restrict__ bih,
    const float* __restrict__ bhh)
{
    __shared__ float As[128][36];
    __shared__ float Bh[64][36], Bl[64][36];

    const int m0 = blockIdx.x * 128;
    const int n0 = blockIdx.y * 64;
    const int tid = threadIdx.x;
    const int warp = tid >> 5;
    const int lane = tid & 31;
    const int g = lane >> 2;
    const int tg = lane & 3;
    const int wm = warp * 16;

    float acc[8][4];
#pragma unroll
    for (int nt = 0; nt < 8; nt++)
#pragma unroll
        for (int i = 0; i < 4; i++) acc[nt][i] = 0.0f;

    for (int kc = 0; kc < 8; kc++) {
        const int k0 = kc * 32;
        __syncthreads();
#pragma unroll
        for (int q = 0; q < 4; q++) {
            int i = tid + 256 * q;
            int row = i >> 3;
            int kq = (i & 7) * 4;
            float4 xv = *(const float4*)(X + (size_t)(m0 + row) * KK + k0 + kq);
            float4 mv = *(const float4*)(MX + (size_t)((m0 + row) & (BB - 1)) * KK + k0 + kq);
            xv.x *= mv.x; xv.y *= mv.y; xv.z *= mv.z; xv.w *= mv.w;
            *(float4*)&As[row][kq] = xv;
        }
#pragma unroll
        for (int q = 0; q < 2; q++) {
            int i = tid + 256 * q;
            int row = i >> 3;
            int kq = (i & 7) * 4;
            float4 wv = *(const float4*)(W + (size_t)(n0 + row) * KK + k0 + kq);
            unsigned h, l;
            split_tf32(wv.x, h, l);
            Bh[row][kq]     = __uint_as_float(h); Bl[row][kq]     = __uint_as_float(l);
            split_tf32(wv.y, h, l);
            Bh[row][kq + 1] = __uint_as_float(h); Bl[row][kq + 1] = __uint_as_float(l);
            split_tf32(wv.z, h, l);
            Bh[row][kq + 2] = __uint_as_float(h); Bl[row][kq + 2] = __uint_as_float(l);
            split_tf32(wv.w, h, l);
            Bh[row][kq + 3] = __uint_as_float(h); Bl[row][kq + 3] = __uint_as_float(l);
        }
        __syncthreads();

#pragma unroll
        for (int ks = 0; ks < 4; ks++) {
            const int kk = ks * 8;
            unsigned ah[4], al[4];
            split_tf32(As[wm + g][kk + tg],         ah[0], al[0]);
            split_tf32(As[wm + g + 8][kk + tg],     ah[1], al[1]);
            split_tf32(As[wm + g][kk + tg + 4],     ah[2], al[2]);
            split_tf32(As[wm + g + 8][kk + tg + 4], ah[3], al[3]);
#pragma unroll
            for (int nt = 0; nt < 8; nt++) {
                unsigned bh0 = __float_as_uint(Bh[nt * 8 + g][kk + tg]);
                unsigned bh1 = __float_as_uint(Bh[nt * 8 + g][kk + tg + 4]);
                unsigned bl0 = __float_as_uint(Bl[nt * 8 + g][kk + tg]);
                unsigned bl1 = __float_as_uint(Bl[nt * 8 + g][kk + tg + 4]);
                mma_tf32(acc[nt], ah, bh0, bh1);
                mma_tf32(acc[nt], ah, bl0, bl1);
                mma_tf32(acc[nt], al, bh0, bh1);
            }
        }
    }

#pragma unroll
    for (int nt = 0; nt < 8; nt++) {
        const int n = n0 + nt * 8 + tg * 2;
        const float bs0 = bih[n] + bhh[n];
        const float bs1 = bih[n + 1] + bhh[n + 1];
        const int m = m0 + wm + g;
        float2 r0 = make_float2(acc[nt][0] + bs0, acc[nt][1] + bs1);
        float2 r1 = make_float2(acc[nt][2] + bs0, acc[nt][3] + bs1);
        *(float2*)&g_gx[(size_t)m * GG + n] = r0;
        *(float2*)&g_gx[(size_t)(m + 8) * GG + n] = r1;
    }
}

// ---------------------------------------------------------------------------
// Grid-wide barrier, RBLK arrivals. All 128 CTAs co-resident: 187KB smem
// forces 1 CTA/SM, and 128 <= 148 SMs.
// ---------------------------------------------------------------------------
__device__ __forceinline__ void grid_barrier()
{
    __threadfence();
    __syncthreads();
    if (threadIdx.x == 0) {
        unsigned gen = *(volatile unsigned*)&g_gen;
        if (atomicAdd(&g_bar, 1u) == (unsigned)(RBLK - 1)) {
            g_bar = 0;
            __threadfence();
            *(volatile unsigned*)&g_gen = gen + 1;
        } else {
            while (*(volatile unsigned*)&g_gen == gen) { }
        }
    }
    __syncthreads();
}

__device__ __forceinline__ float fsig(float x) {
    return __fdividef(1.0f, 1.0f + __expf(-x));
}
__device__ __forceinline__ float ftanh(float x) {
    return __fdividef(2.0f, 1.0f + __expf(-2.0f * x)) - 1.0f;
}

// ---------------------------------------------------------------------------
// Tensor-core persistent recurrence.
//   128 CTAs = 8 batch-groups (32 rows) x 16 n-blocks (16 j x 4 gates = 64 n).
//   W_hh n-slice split tf32 hi/lo ONCE into smem ([kc][64][36], R12 layout).
//   Per step: hm tile (32x256) -> smem raw, one sync; warps compute 16 16x8
//   output tiles via 3-term split-tf32 MMA (A split in-loop, R12-proven);
//   accs staged through smem; pointwise identical to prior rounds.
// Dynamic smem floats:
//   Wh 8*64*36=18432 | Wl 18432 | As 32*260=8320 | STG 32*68=2176 | bsz 512
// ---------------------------------------------------------------------------
#define SM_WH   0
#define SM_WL   18432
#define SM_AS   36864
#define SM_STG  45184
#define SM_BSZ  47360
#define SM_FLOATS 47872   // 191488 bytes

__global__ __launch_bounds__(RTHR) void recurrent_tc(
    const float* __restrict__ mh, const float* __restrict__ Whh,
    const int* __restrict__ bsz, const float* __restrict__ h0,
    const float* __restrict__ c0, float* __restrict__ out)
{
    extern __shared__ float sm[];
    float* Wh = sm + SM_WH;
    float* Wl = sm + SM_WL;
    float* As = sm + SM_AS;    // [32][260] raw hm
    float* STG = sm + SM_STG;  // [32][68] gate staging
    int* SB = (int*)(sm + SM_BSZ);

    const int bb = blockIdx.x >> 4;   // batch group 0..7
    const int nb = blockIdx.x & 15;   // n-block 0..15
    const int b0 = bb * 32;
    const int j0 = nb * 16;
    const int tid = threadIdx.x;
    const int warp = tid >> 5;
    const int lane = tid & 31;
    const int g = lane >> 2;
    const int tg = lane & 3;
    const int wm = (warp & 1) * 16;        // warp's M-tile (rows wm..wm+15)
    const int np = (warp >> 1) * 16;       // warp's n-local base (2 tiles of 8)

    // ---- one-time: split W_hh slice into Wh/Wl [kc][nloc][36] ----
    for (int i = tid; i < 64 * 256; i += RTHR) {
        int nloc = i >> 8;                 // 0..63: gate = nloc>>4, jl = nloc&15
        int k = i & 255;
        int nglob = (nloc >> 4) * 256 + j0 + (nloc & 15);
        unsigned h, l;
        split_tf32(Whh[(size_t)nglob * KK + k], h, l);
        int idx = ((k >> 5) * 64 + nloc) * 36 + (k & 31);
        Wh[idx] = __uint_as_float(h);
        Wl[idx] = __uint_as_float(l);
    }
    for (int i = tid; i < TT; i += RTHR) SB[i] = bsz[i];

    // ---- one-time: register state: 2 cells (b0+bl0, j), (b0+bl0+16, j) ----
    const int jl = tid & 15;
    const int bl0 = tid >> 4;              // 0..15
    const int j = j0 + jl;
    float mhv[2], cc[2], hh[2];
#pragma unroll
    for (int r = 0; r < 2; r++) {
        int b = b0 + bl0 + 16 * r;
        mhv[r] = mh[b * HH + j];
        cc[r] = c0[b * HH + j];
        hh[r] = h0[b * HH + j];
        g_hm[0][b * HH + j] = hh[r] * mhv[r];
    }
    __syncthreads();
    grid_barrier();    // hm[0] + all CTAs' W splits ready

    // A loader mapping: 32 rows x 256 k, 8 float4 per thread
    const int arow = tid >> 3;
    const int akq = (tid & 7) * 4;

    // prefetch gx(0): [r][gate]
    float gx[2][4];
#pragma unroll
    for (int r = 0; r < 2; r++) {
        const float* gp = g_gx + (size_t)(b0 + bl0 + 16 * r) * GG + j;
#pragma unroll
        for (int q = 0; q < 4; q++) gx[r][q] = __ldcg(gp + q * 256);
    }

    for (int t = 0; t < TT; t++) {
        const float* __restrict__ hmp = g_hm[t & 1];
        float* __restrict__ hmn = g_hm[(t & 1) ^ 1];

        // load hm tile (raw fp32)
        {
            const float* src = hmp + (size_t)(b0 + arow) * HH + akq;
#pragma unroll
            for (int q = 0; q < 8; q++)
                *(float4*)&As[arow * 260 + akq + q * 32] = __ldcg((const float4*)(src + q * 32));
        }
        __syncthreads();

        // MMA: 2 output tiles per warp, K=256 in 32 k8-steps
        float acc0[4] = {0.f, 0.f, 0.f, 0.f};
        float acc1[4] = {0.f, 0.f, 0.f, 0.f};
        for (int kc = 0; kc < 8; kc++) {
#pragma unroll
            for (int ks = 0; ks < 4; ks++) {
                const int kk = ks * 8;
                const int kg = kc * 32 + kk;
                unsigned ah[4], al[4];
                split_tf32(As[(wm + g) * 260 + kg + tg],         ah[0], al[0]);
                split_tf32(As[(wm + g + 8) * 260 + kg + tg],     ah[1], al[1]);
                split_tf32(As[(wm + g) * 260 + kg + tg + 4],     ah[2], al[2]);
                split_tf32(As[(wm + g + 8) * 260 + kg + tg + 4], ah[3], al[3]);
                {
                    const int wbase = ((kc * 64) + np + g) * 36 + kk + tg;
                    unsigned bh0 = __float_as_uint(Wh[wbase]);
                    unsigned bh1 = __float_as_uint(Wh[wbase + 4]);
                    unsigned bl0_ = __float_as_uint(Wl[wbase]);
                    unsigned bl1_ = __float_as_uint(Wl[wbase + 4]);
                    mma_tf32(acc0, ah, bh0, bh1);
                    mma_tf32(acc0, ah, bl0_, bl1_);
                    mma_tf32(acc0, al, bh0, bh1);
                }
                {
                    const int wbase = ((kc * 64) + np + 8 + g) * 36 + kk + tg;
                    unsigned bh0 = __float_as_uint(Wh[wbase]);
                    unsigned bh1 = __float_as_uint(Wh[wbase + 4]);
                    unsigned bl0_ = __float_as_uint(Wl[wbase]);
                    unsigned bl1_ = __float_as_uint(Wl[wbase + 4]);
                    mma_tf32(acc1, ah, bh0, bh1);
                    mma_tf32(acc1, ah, bl0_, bl1_);
                    mma_tf32(acc1, al, bh0, bh1);
                }
            }
        }

        // stage accumulators: STG[row][nloc]
        {
            int nc0 = np + tg * 2;
            *(float2*)&STG[(wm + g) * 68 + nc0]     = make_float2(acc0[0], acc0[1]);
            *(float2*)&STG[(wm + g + 8) * 68 + nc0] = make_float2(acc0[2], acc0[3]);
            int nc1 = np + 8 + tg * 2;
            *(float2*)&STG[(wm + g) * 68 + nc1]     = make_float2(acc1[0], acc1[1]);
            *(float2*)&STG[(wm + g + 8) * 68 + nc1] = make_float2(acc1[2], acc1[3]);
        }
        __syncthreads();

        // pointwise: 2 owned cells; nloc = gate*16 + jl
        const int size = SB[t];
        float o[2];
#pragma unroll
        for (int r = 0; r < 2; r++) {
            const int bl = bl0 + 16 * r;
            const int b = b0 + bl;
            float a0 = STG[bl * 68 + jl]      + gx[r][0];
            float a1 = STG[bl * 68 + 16 + jl] + gx[r][1];
            float a2 = STG[bl * 68 + 32 + jl] + gx[r][2];
            float a3 = STG[bl * 68 + 48 + jl] + gx[r][3];
            float iv = fsig(a0), fv = fsig(a1), gv = ftanh(a2), ov = fsig(a3);
            float cn = fv * cc[r] + iv * gv;
            float hn = ov * ftanh(cn);
            bool act = b < size;
            if (act) { cc[r] = cn; hh[r] = hn; }
            o[r] = act ? hn : 0.0f;
            hmn[b * HH + j] = hh[r] * mhv[r];
        }

        // prefetch gx(t+1)
        if (t + 1 < TT) {
#pragma unroll
            for (int r = 0; r < 2; r++) {
                const float* gp = g_gx + ((size_t)(t + 1) * BB + b0 + bl0 + 16 * r) * GG + j;
#pragma unroll
                for (int q = 0; q < 4; q++) gx[r][q] = __ldcg(gp + q * 256);
            }
        }

        grid_barrier();

#pragma unroll
        for (int r = 0; r < 2; r++)
            out[((size_t)t * BB + b0 + bl0 + 16 * r) * HH + j] = o[r];
    }

    // final hn, cn
    const size_t TBH = (size_t)TT * BB * HH;
#pragma unroll
    for (int r = 0; r < 2; r++) {
        int b = b0 + bl0 + 16 * r;
        out[TBH + b * HH + j] = hh[r];
        out[TBH + BB * HH + b * HH + j] = cc[r];
    }
}

// ---------------------------------------------------------------------------
extern "C" void kernel_launch(void* const* d_in, const int* in_sizes, int n_in,
                              void* d_out, int out_size)
{
    const float* X   = (const float*)d_in[0];   // [T,B,D]
    const float* h0  = (const float*)d_in[1];   // [B,H]
    const float* c0  = (const float*)d_in[2];   // [B,H]
    const float* mx  = (const float*)d_in[3];   // [B,D]
    const float* mh  = (const float*)d_in[4];   // [B,H]
    const float* Wih = (const float*)d_in[5];   // [4H,D]
    const float* Whh = (const float*)d_in[6];   // [4H,H]
    const float* bih = (const float*)d_in[7];   // [4H]
    const float* bhh = (const float*)d_in[8];   // [4H]
    const int*   bsz = (const int*)d_in[9];     // [T]
    float* out = (float*)d_out;                 // [T*B*H] ++ [B*H] ++ [B*H]

    static int smem_set = 0;
    if (!smem_set) {
        cudaFuncSetAttribute(recurrent_tc,
                             cudaFuncAttributeMaxDynamicSharedMemorySize,
                             SM_FLOATS * 4);
        smem_set = 1;
    }

    gemm_x_tc<<<dim3((TT * BB) / 128, GG / 64), 256>>>(X, mx, Wih, bih, bhh);
    recurrent_tc<<<RBLK, RTHR, SM_FLOATS * 4>>>(mh, Whh, bsz, h0, c0, out);
}